// round 3
// baseline (speedup 1.0000x reference)
#include <cuda_runtime.h>
#include <cstdint>

#define DIMD 256
#define NEMB 512
#define TM 128
#define AS_STRIDE 132   // 132*4B row stride: 16B-aligned rows, low STS conflict

__device__ __align__(16) float  g_EN [NEMB * DIMD];   // normalized codebook [j][d]
__device__ __align__(16) float  g_ENT[DIMD * NEMB];   // transposed         [d][j]
__device__ __align__(16) float  g_C  [NEMB];          // c_j = sum(e_hat^2)
__device__ double g_entropy;
__device__ double g_partials[2048];

// ---------------- Phase A1: normalize codebook rows ----------------
__global__ void k_norm(const float* __restrict__ emb) {
    int j = blockIdx.x;      // 0..511
    int t = threadIdx.x;     // 0..63
    __shared__ float red[64];
    float4 v = reinterpret_cast<const float4*>(emb + j * DIMD)[t];
    red[t] = v.x * v.x + v.y * v.y + v.z * v.z + v.w * v.w;
    __syncthreads();
    for (int o = 32; o > 0; o >>= 1) { if (t < o) red[t] += red[t + o]; __syncthreads(); }
    float nrm = sqrtf(red[0]);
    __syncthreads();
    float4 q;
    q.x = v.x / nrm; q.y = v.y / nrm; q.z = v.z / nrm; q.w = v.w / nrm;
    reinterpret_cast<float4*>(g_EN + j * DIMD)[t] = q;
    int d = t * 4;
    g_ENT[(d + 0) * NEMB + j] = q.x;
    g_ENT[(d + 1) * NEMB + j] = q.y;
    g_ENT[(d + 2) * NEMB + j] = q.z;
    g_ENT[(d + 3) * NEMB + j] = q.w;
    red[t] = q.x * q.x + q.y * q.y + q.z * q.z + q.w * q.w;
    __syncthreads();
    for (int o = 32; o > 0; o >>= 1) { if (t < o) red[t] += red[t + o]; __syncthreads(); }
    if (t == 0) g_C[j] = red[0];
}

// ---------------- Phase A2: entropy = 2E*sum(c) - 2*||sum_j e_hat_j||^2 ----
__global__ void k_entropy() {
    int t = threadIdx.x;  // 256
    float s = 0.f;
    for (int j = 0; j < NEMB; j++) s += g_EN[j * DIMD + t];
    double val = 2.0 * (double)NEMB * ((double)g_C[t] + (double)g_C[t + 256])
               - 2.0 * (double)s * (double)s;
    __shared__ double red[256];
    red[t] = val; __syncthreads();
    for (int o = 128; o > 0; o >>= 1) { if (t < o) red[t] += red[t + o]; __syncthreads(); }
    if (t == 0) g_entropy = red[0];
}

// ---------------- packed f32x2 helpers (Blackwell FFMA2 path) ----------------
__device__ __forceinline__ unsigned long long pack2(float a) {
    unsigned long long r;
    asm("mov.b64 %0, {%1, %1};" : "=l"(r) : "f"(a));
    return r;
}
__device__ __forceinline__ void fma2(unsigned long long& c, unsigned long long a,
                                     unsigned long long b) {
    asm("fma.rn.f32x2 %0, %1, %2, %0;" : "+l"(c) : "l"(a), "l"(b));
}

#define CP16(dst, src) asm volatile("cp.async.cg.shared.global [%0], [%1], 16;" :: "r"(dst), "l"(src))
#define CP_COMMIT()    asm volatile("cp.async.commit_group;")
#define CP_WAIT(n)     asm volatile("cp.async.wait_group %0;" :: "n"(n))

__device__ __forceinline__ void prefetchB(float* BsBuf, int j0, int kbase, int tid) {
#pragma unroll
    for (int i = 0; i < 2; i++) {
        int idx = tid + i * 256;
        int k   = idx >> 5;     // 0..15
        int j4  = idx & 31;     // 0..31
        const float* src = g_ENT + (size_t)(kbase + k) * NEMB + j0 + j4 * 4;
        unsigned dst = (unsigned)__cvta_generic_to_shared(BsBuf + k * 128 + j4 * 4);
        CP16(dst, src);
    }
}

// ---------------- Main: fused GEMM + argmin + gather + diff ----------------
__global__ void __launch_bounds__(256, 1) k_main(
        const float* __restrict__ input,
        float* __restrict__ out,
        float* __restrict__ ind_out)
{
    extern __shared__ float smem[];
    float*  As   = smem;                      // [256][AS_STRIDE] k-major A tile
    float*  Bs   = smem + DIMD * AS_STRIDE;   // [2][16][128] double-buffered B
    float*  sc   = Bs + 2 * 16 * 128;         // [512] c_j cache
    int*    sInd = (int*)(sc + NEMB);         // [128]
    float*  sSq  = (float*)(sInd + TM);       // [128] fp32 row-norm^2 (ref scale)
    double* dred = (double*)(sSq + TM);       // [256]

    const int  tid = threadIdx.x;
    const long r0  = (long)blockIdx.x * TM;
    const int  w = tid >> 5, l = tid & 31;
    const int  r2 = l & 7, c2 = l >> 3;

    for (int i = tid; i < NEMB; i += 256) sc[i] = g_C[i];

    // load + transpose A into smem (k-major), 2-way STS conflicts only
#pragma unroll
    for (int itr = 0; itr < 2; itr++)
#pragma unroll 4
        for (int itc = 0; itc < 16; itc++) {
            int row = w * 8 + r2 + itr * 64;
            int c4  = itc * 4 + c2;
            float4 v = *reinterpret_cast<const float4*>(input + (r0 + row) * DIMD + c4 * 4);
            int k = c4 * 4;
            As[(k + 0) * AS_STRIDE + row] = v.x;
            As[(k + 1) * AS_STRIDE + row] = v.y;
            As[(k + 2) * AS_STRIDE + row] = v.z;
            As[(k + 3) * AS_STRIDE + row] = v.w;
        }

    const int tx = tid & 15, ty = tid >> 4;

    float bestS[8];
    int   bestI[8];
#pragma unroll
    for (int i = 0; i < 8; i++) { bestS[i] = 3.0e38f; bestI[i] = 0; }

    __syncthreads();  // As + sc visible

    // ---- per-row ||x||^2 in double, rounded to fp32 (matches ref dist scale)
    {
        int row  = tid & 127;
        int half = tid >> 7;                  // 0 or 1
        const float* Ar = As + row + half * 128 * AS_STRIDE;
        double acc = 0.0;
#pragma unroll 8
        for (int k = 0; k < 128; k++) {
            double a = (double)Ar[k * AS_STRIDE];
            acc += a * a;
        }
        dred[tid] = acc;
    }
    __syncthreads();
    if (tid < TM) sSq[tid] = (float)(dred[tid] + dred[tid + 128]);
    __syncthreads();

    for (int jt = 0; jt < 4; jt++) {
        const int j0 = jt * 128;
        unsigned long long acc[8][4];
#pragma unroll
        for (int i = 0; i < 8; i++)
#pragma unroll
            for (int jj = 0; jj < 4; jj++) acc[i][jj] = 0ULL;

        prefetchB(Bs, j0, 0, tid);
        CP_COMMIT();

        for (int kt = 0; kt < 16; kt++) {
            if (kt < 15) {
                prefetchB(Bs + ((kt + 1) & 1) * 2048, j0, (kt + 1) * 16, tid);
                CP_COMMIT();
                CP_WAIT(1);
            } else {
                CP_WAIT(0);
            }
            __syncthreads();
            const float* Bc = Bs + (kt & 1) * 2048;
            const float* Ak = As + kt * 16 * AS_STRIDE;
#pragma unroll
            for (int kk = 0; kk < 16; kk++) {
                float4 a0 = *reinterpret_cast<const float4*>(Ak + kk * AS_STRIDE + ty * 8);
                float4 a1 = *reinterpret_cast<const float4*>(Ak + kk * AS_STRIDE + ty * 8 + 4);
                ulonglong2 b01 = *reinterpret_cast<const ulonglong2*>(Bc + kk * 128 + tx * 8);
                ulonglong2 b23 = *reinterpret_cast<const ulonglong2*>(Bc + kk * 128 + tx * 8 + 4);
                const unsigned long long bp0 = b01.x, bp1 = b01.y, bp2 = b23.x, bp3 = b23.y;
                float av[8] = {a0.x, a0.y, a0.z, a0.w, a1.x, a1.y, a1.z, a1.w};
#pragma unroll
                for (int i = 0; i < 8; i++) {
                    unsigned long long ap = pack2(av[i]);
                    fma2(acc[i][0], ap, bp0);
                    fma2(acc[i][1], ap, bp1);
                    fma2(acc[i][2], ap, bp2);
                    fma2(acc[i][3], ap, bp3);
                }
            }
            __syncthreads();
        }

        // fold this j-tile into running argmin, replicating the reference's
        // fp32 rounding: dist = fl( fl(sq - fl(2*dot)) + c_j )  (no FMA fusion)
#pragma unroll
        for (int i = 0; i < 8; i++) {
            float sqr = sSq[ty * 8 + i];
#pragma unroll
            for (int jj = 0; jj < 4; jj++) {
                float2 d = *reinterpret_cast<float2*>(&acc[i][jj]);
                int j = j0 + tx * 8 + jj * 2;
                float s0 = __fadd_rn(__fsub_rn(sqr, __fmul_rn(2.0f, d.x)), sc[j]);
                float s1 = __fadd_rn(__fsub_rn(sqr, __fmul_rn(2.0f, d.y)), sc[j + 1]);
                if (s0 < bestS[i]) { bestS[i] = s0; bestI[i] = j; }
                if (s1 < bestS[i]) { bestS[i] = s1; bestI[i] = j + 1; }
            }
        }
    }

    // cross-thread argmin over the 16-lane row group (xor<16 stays in half-warp)
    const unsigned mask = 0xFFFFFFFFu;
#pragma unroll
    for (int i = 0; i < 8; i++) {
        float s = bestS[i]; int bi = bestI[i];
#pragma unroll
        for (int o = 8; o > 0; o >>= 1) {
            float so = __shfl_xor_sync(mask, s, o);
            int   io = __shfl_xor_sync(mask, bi, o);
            if (so < s || (so == s && io < bi)) { s = so; bi = io; }
        }
        bestS[i] = s; bestI[i] = bi;
    }
    if (tx == 0) {
#pragma unroll
        for (int i = 0; i < 8; i++) {
            int r = ty * 8 + i;
            sInd[r] = bestI[i];
            ind_out[r0 + r] = (float)bestI[i];
        }
    }
    __syncthreads();

    // gather normalized codes -> out, accumulate sum((q-x)^2)
    float fsum = 0.f;
#pragma unroll
    for (int itr = 0; itr < 2; itr++)
        for (int itc = 0; itc < 16; itc++) {
            int row = w * 8 + r2 + itr * 64;
            int c4  = itc * 4 + c2;
            int jb  = sInd[row];
            float4 q = *reinterpret_cast<const float4*>(g_EN + jb * DIMD + c4 * 4);
            float4 x = *reinterpret_cast<const float4*>(input + (r0 + row) * DIMD + c4 * 4);
            *reinterpret_cast<float4*>(out + (r0 + row) * DIMD + c4 * 4) = q;
            float dx = q.x - x.x, dy = q.y - x.y, dz = q.z - x.z, dw = q.w - x.w;
            fsum += dx * dx + dy * dy + dz * dz + dw * dw;
        }

    dred[tid] = (double)fsum;
    __syncthreads();
    for (int o = 128; o > 0; o >>= 1) { if (tid < o) dred[tid] += dred[tid + o]; __syncthreads(); }
    if (tid == 0) g_partials[blockIdx.x] = dred[0];
}

// ---------------- final: loss = diff - entropy/E^2 ----------------
__global__ void k_final(float* __restrict__ loss_out, int nblocks, long n) {
    __shared__ double red[256];
    int t = threadIdx.x;
    double s = 0.0;
    for (int i = t; i < nblocks; i += 256) s += g_partials[i];
    red[t] = s; __syncthreads();
    for (int o = 128; o > 0; o >>= 1) { if (t < o) red[t] += red[t + o]; __syncthreads(); }
    if (t == 0) {
        double diff = red[0] / (double)n;
        double loss = diff - g_entropy / ((double)NEMB * (double)NEMB);
        loss_out[0] = (float)loss;
    }
}

extern "C" void kernel_launch(void* const* d_in, const int* in_sizes, int n_in,
                              void* d_out, int out_size) {
    const float* input = (const float*)d_in[0];
    const float* emb   = (const float*)d_in[1];
    long n      = (long)in_sizes[0];       // B*T*D = 33554432
    int  nrows  = (int)(n / DIMD);         // 131072
    int  nblk   = nrows / TM;              // 1024
    float* out    = (float*)d_out;
    float* loss_p = out + n;               // layout: [out | loss | embed_ind]
    float* ind_p  = out + n + 1;

    size_t smem = (size_t)(DIMD * AS_STRIDE + 2 * 16 * 128 + NEMB) * sizeof(float)
                + TM * sizeof(int) + TM * sizeof(float) + 256 * sizeof(double);
    cudaFuncSetAttribute(k_main, cudaFuncAttributeMaxDynamicSharedMemorySize, (int)smem);

    k_norm   <<<NEMB, 64>>>(emb);
    k_entropy<<<1, 256>>>();
    k_main   <<<nblk, 256, smem>>>(input, out, ind_p);
    k_final  <<<1, 256>>>(loss_p, nblk, n);
}

// round 7
// speedup vs baseline: 1.5178x; 1.5178x over previous
#include <cuda_runtime.h>
#include <cuda_bf16.h>
#include <cstdint>

#define DIMD 256
#define NEMB 512
#define TM   128
#define MARGIN 0.25f
#define CAND_CAP 16

__device__ __align__(16) float          g_EN [NEMB * DIMD];  // normalized codebook f32 [j][k]
__device__ __align__(16) float          g_C  [NEMB];         // c_j
__device__ __align__(16) unsigned short g_Bbf[NEMB * DIMD];  // bf16 codebook [j][k]
__device__ double g_entropy;
__device__ double g_partials[2048];

// ---- smem layout (byte offsets) ----
#define A_STRIDE  528u              // 264 halves: bank stride 4 -> ldmatrix conflict-free
#define A_OFF     0u                // 128 * 528 = 67584
#define B_OFF     67584u            // 2 bufs x 67584 = 135168
#define B_BUFSZ   67584u
#define SC_OFF    202752u           // 512 f
#define SSQ_OFF   204800u           // 128 f
#define SIND_OFF  205312u           // 128 i
#define CCNT_OFF  205824u           // 128 i
#define CLIST_OFF 206336u           // 128 * 16 i = 8192
#define DRED_OFF  214528u           // 256 d
#define SMEM_REQ  216576u

#define CP16(dst, src) asm volatile("cp.async.cg.shared.global [%0], [%1], 16;" :: "r"(dst), "l"(src))
#define CP_COMMIT()    asm volatile("cp.async.commit_group;")
#define CP_WAIT(n)     asm volatile("cp.async.wait_group %0;" :: "n"(n))

#define LDM_X4(r0, r1, r2, r3, a) \
    asm volatile("ldmatrix.sync.aligned.m8n8.x4.shared.b16 {%0,%1,%2,%3}, [%4];" \
                 : "=r"(r0), "=r"(r1), "=r"(r2), "=r"(r3) : "r"(a))

#define MMA_BF16(c, a0, a1, a2, a3, b0, b1) \
    asm volatile("mma.sync.aligned.m16n8k16.row.col.f32.bf16.bf16.f32 " \
                 "{%0,%1,%2,%3}, {%4,%5,%6,%7}, {%8,%9}, {%0,%1,%2,%3};" \
                 : "+f"((c)[0]), "+f"((c)[1]), "+f"((c)[2]), "+f"((c)[3]) \
                 : "r"(a0), "r"(a1), "r"(a2), "r"(a3), "r"(b0), "r"(b1))

__device__ __forceinline__ uint32_t bf16x2_of(float lo, float hi) {
    uint32_t r;
    asm("cvt.rn.bf16x2.f32 %0, %1, %2;" : "=r"(r) : "f"(hi), "f"(lo));  // %2 -> low half
    return r;
}

// ---------------- Phase A1: normalize codebook rows (R2-proven) ----------------
__global__ void k_norm(const float* __restrict__ emb) {
    int j = blockIdx.x, t = threadIdx.x;  // 512 x 64
    __shared__ float red[64];
    float4 v = reinterpret_cast<const float4*>(emb + j * DIMD)[t];
    red[t] = v.x * v.x + v.y * v.y + v.z * v.z + v.w * v.w;
    __syncthreads();
    for (int o = 32; o > 0; o >>= 1) { if (t < o) red[t] += red[t + o]; __syncthreads(); }
    float nrm = sqrtf(red[0]);
    __syncthreads();
    float4 q;
    q.x = v.x / nrm; q.y = v.y / nrm; q.z = v.z / nrm; q.w = v.w / nrm;
    reinterpret_cast<float4*>(g_EN + j * DIMD)[t] = q;
    red[t] = q.x * q.x + q.y * q.y + q.z * q.z + q.w * q.w;
    __syncthreads();
    for (int o = 32; o > 0; o >>= 1) { if (t < o) red[t] += red[t + o]; __syncthreads(); }
    if (t == 0) g_C[j] = red[0];
}

// ---------------- Phase A2: entropy (R2-proven) ----------------
__global__ void k_entropy() {
    int t = threadIdx.x;  // 256
    float s = 0.f;
    for (int j = 0; j < NEMB; j++) s += g_EN[j * DIMD + t];
    double val = 2.0 * (double)NEMB * ((double)g_C[t] + (double)g_C[t + 256])
               - 2.0 * (double)s * (double)s;
    __shared__ double red[256];
    red[t] = val; __syncthreads();
    for (int o = 128; o > 0; o >>= 1) { if (t < o) red[t] += red[t + o]; __syncthreads(); }
    if (t == 0) g_entropy = red[0];
}

// ---------------- Phase A3: bf16 codebook ----------------
__global__ void k_prepB() {
    int idx = blockIdx.x * 256 + threadIdx.x;   // 131072
    float x = g_EN[idx];
    unsigned short h;
    asm("cvt.rn.bf16.f32 %0, %1;" : "=h"(h) : "f"(x));
    g_Bbf[idx] = h;
}

// exact rescore: serial ascending-k fmaf chain == R2's passing arithmetic
__device__ __forceinline__ float rescore(const float* __restrict__ input, long grow,
                                         int j, float cj, float sqr) {
    const float4* xp = reinterpret_cast<const float4*>(input + grow * DIMD);
    const float4* ep = reinterpret_cast<const float4*>(g_EN + j * DIMD);
    float d = 0.f;
#pragma unroll 8
    for (int k = 0; k < 64; k++) {
        float4 x = xp[k], e = ep[k];
        d = __fmaf_rn(x.x, e.x, d); d = __fmaf_rn(x.y, e.y, d);
        d = __fmaf_rn(x.z, e.z, d); d = __fmaf_rn(x.w, e.w, d);
    }
    return __fadd_rn(__fsub_rn(sqr, __fmul_rn(2.0f, d)), cj);
}

// ---------------- Main: bf16 mma.sync GEMM + filter + exact rescore ----------
__global__ void __launch_bounds__(256, 1) k_main(
        const float* __restrict__ input,
        float* __restrict__ out,
        float* __restrict__ ind_out)
{
    extern __shared__ char smraw[];
    uint32_t raw32 = (uint32_t)__cvta_generic_to_shared(smraw);
    float*  sc    = (float*)(smraw + SC_OFF);
    float*  sSq   = (float*)(smraw + SSQ_OFF);
    int*    sInd  = (int*)(smraw + SIND_OFF);
    int*    cCnt  = (int*)(smraw + CCNT_OFF);
    int*    cList = (int*)(smraw + CLIST_OFF);
    double* dred  = (double*)(smraw + DRED_OFF);

    const int  tid  = threadIdx.x;
    const int  wid  = tid >> 5, lane = tid & 31;
    const long r0   = (long)blockIdx.x * TM;

    if (tid < TM) cCnt[tid] = 0;
    for (int i = tid; i < NEMB; i += 256) sc[i] = g_C[i];

    // ---- A load: f32 -> bf16 into padded smem; exact double row norms ----
    {
        int r = tid >> 1, h = tid & 1;
        const float4* src = reinterpret_cast<const float4*>(input + (r0 + r) * DIMD + h * 128);
        uint32_t dst = raw32 + A_OFF + (uint32_t)r * A_STRIDE + (uint32_t)h * 256u;
        double dsq = 0.0;
#pragma unroll 8
        for (int q = 0; q < 32; q++) {
            float4 v = src[q];
            dsq += (double)v.x * v.x + (double)v.y * v.y + (double)v.z * v.z + (double)v.w * v.w;
            uint32_t p0 = bf16x2_of(v.x, v.y);
            uint32_t p1 = bf16x2_of(v.z, v.w);
            asm volatile("st.shared.v2.b32 [%0], {%1, %2};" :: "r"(dst + q * 8u), "r"(p0), "r"(p1));
        }
        dred[tid] = dsq;
    }
    // prefetch B chunk 0
    {
#pragma unroll
        for (int q = 0; q < 16; q++) {
            int idx = tid + q * 256;
            int row = idx >> 5, seg = idx & 31;
            CP16(raw32 + B_OFF + (uint32_t)row * A_STRIDE + (uint32_t)seg * 16u,
                 (const char*)g_Bbf + (size_t)row * 512 + seg * 16);
        }
        CP_COMMIT();
    }
    __syncthreads();
    if (tid < TM) sSq[tid] = (float)(dred[2 * tid] + dred[2 * tid + 1]);
    __syncthreads();

    // ---- per-lane fragment address precompute ----
    const int tquad = lane >> 3, rr = lane & 7;
    const uint32_t aAddrBase = raw32 + A_OFF
        + (uint32_t)(wid * 16 + ((tquad & 1) << 3) + rr) * A_STRIDE
        + (uint32_t)(((tquad >> 1) << 3) * 2);
    const uint32_t bLanePart = (uint32_t)(((tquad >> 1) * 8 + rr) * A_STRIDE + ((tquad & 1) << 3) * 2);

    const float sqrA = sSq[wid * 16 + (lane >> 2)];
    const float sqrB = sSq[wid * 16 + (lane >> 2) + 8];
    const int   rAl  = wid * 16 + (lane >> 2);
    const int   rBl  = rAl + 8;
    float bsA = 3.0e38f, bsB = 3.0e38f;

    for (int ch = 0; ch < 4; ch++) {
        // prefetch next chunk into other buffer (buffer reuse is 2 chunks apart; safe)
        if (ch < 3) {
#pragma unroll
            for (int q = 0; q < 16; q++) {
                int idx = tid + q * 256;
                int row = idx >> 5, seg = idx & 31;
                CP16(raw32 + B_OFF + (uint32_t)((ch + 1) & 1) * B_BUFSZ
                         + (uint32_t)row * A_STRIDE + (uint32_t)seg * 16u,
                     (const char*)g_Bbf + (size_t)((ch + 1) * 128 + row) * 512 + seg * 16);
            }
            CP_COMMIT();
            CP_WAIT(1);
        } else {
            CP_WAIT(0);
        }
        __syncthreads();

        const uint32_t bBuf = raw32 + B_OFF + (uint32_t)(ch & 1) * B_BUFSZ + bLanePart;
        float acc[16][4];
#pragma unroll
        for (int i = 0; i < 16; i++) { acc[i][0] = acc[i][1] = acc[i][2] = acc[i][3] = 0.f; }

#pragma unroll 2
        for (int kk = 0; kk < 16; kk++) {
            uint32_t a0, a1, a2, a3;
            LDM_X4(a0, a1, a2, a3, aAddrBase + (uint32_t)kk * 32u);
#pragma unroll
            for (int ntp = 0; ntp < 8; ntp++) {
                uint32_t b0, b1, b2, b3;
                LDM_X4(b0, b1, b2, b3, bBuf + (uint32_t)ntp * (16u * A_STRIDE) + (uint32_t)kk * 32u);
                MMA_BF16(acc[ntp * 2],     a0, a1, a2, a3, b0, b1);
                MMA_BF16(acc[ntp * 2 + 1], a0, a1, a2, a3, b2, b3);
            }
        }

        // ---- epilogue sweep 1: fold into running per-row best (approx scores) ----
        const int jbase = ch * 128 + 2 * (lane & 3);
#pragma unroll
        for (int nt = 0; nt < 16; nt++) {
            int j0 = jbase + nt * 8;
            float sA0 = __fadd_rn(__fsub_rn(sqrA, __fmul_rn(2.f, acc[nt][0])), sc[j0]);
            float sA1 = __fadd_rn(__fsub_rn(sqrA, __fmul_rn(2.f, acc[nt][1])), sc[j0 + 1]);
            float sB0 = __fadd_rn(__fsub_rn(sqrB, __fmul_rn(2.f, acc[nt][2])), sc[j0]);
            float sB1 = __fadd_rn(__fsub_rn(sqrB, __fmul_rn(2.f, acc[nt][3])), sc[j0 + 1]);
            bsA = fminf(bsA, fminf(sA0, sA1));
            bsB = fminf(bsB, fminf(sB0, sB1));
        }
        // quad-min (lanes sharing the same two rows)
        float qA = bsA, qB = bsB;
        qA = fminf(qA, __shfl_xor_sync(0xFFFFFFFFu, qA, 1));
        qA = fminf(qA, __shfl_xor_sync(0xFFFFFFFFu, qA, 2));
        qB = fminf(qB, __shfl_xor_sync(0xFFFFFFFFu, qB, 1));
        qB = fminf(qB, __shfl_xor_sync(0xFFFFFFFFu, qB, 2));
        const float thrA = qA + MARGIN, thrB = qB + MARGIN;

        // ---- epilogue sweep 2: push margin candidates ----
#pragma unroll
        for (int nt = 0; nt < 16; nt++) {
            int j0 = jbase + nt * 8;
            float sA0 = __fadd_rn(__fsub_rn(sqrA, __fmul_rn(2.f, acc[nt][0])), sc[j0]);
            float sA1 = __fadd_rn(__fsub_rn(sqrA, __fmul_rn(2.f, acc[nt][1])), sc[j0 + 1]);
            float sB0 = __fadd_rn(__fsub_rn(sqrB, __fmul_rn(2.f, acc[nt][2])), sc[j0]);
            float sB1 = __fadd_rn(__fsub_rn(sqrB, __fmul_rn(2.f, acc[nt][3])), sc[j0 + 1]);
            if (sA0 <= thrA) { int p = atomicAdd(&cCnt[rAl], 1); if (p < CAND_CAP) cList[rAl * CAND_CAP + p] = j0; }
            if (sA1 <= thrA) { int p = atomicAdd(&cCnt[rAl], 1); if (p < CAND_CAP) cList[rAl * CAND_CAP + p] = j0 + 1; }
            if (sB0 <= thrB) { int p = atomicAdd(&cCnt[rBl], 1); if (p < CAND_CAP) cList[rBl * CAND_CAP + p] = j0; }
            if (sB1 <= thrB) { int p = atomicAdd(&cCnt[rBl], 1); if (p < CAND_CAP) cList[rBl * CAND_CAP + p] = j0 + 1; }
        }
        __syncthreads();
    }

    // ---- exact rescore of candidates (2 threads per row) ----
    {
        int row = tid >> 1, h = tid & 1;
        int cnt = cCnt[row];
        float bs = 3.0e38f; int bi = NEMB;
        if (cnt <= CAND_CAP) {
            for (int i = h; i < cnt; i += 2) {
                int j = cList[row * CAND_CAP + i];
                float s = rescore(input, r0 + row, j, sc[j], sSq[row]);
                if (s < bs || (s == bs && j < bi)) { bs = s; bi = j; }
            }
        } else {  // overflow fallback: exact scan of all 512
            for (int j = h; j < NEMB; j += 2) {
                float s = rescore(input, r0 + row, j, sc[j], sSq[row]);
                if (s < bs || (s == bs && j < bi)) { bs = s; bi = j; }
            }
        }
        float os = __shfl_xor_sync(0xFFFFFFFFu, bs, 1);
        int   oi = __shfl_xor_sync(0xFFFFFFFFu, bi, 1);
        if (os < bs || (os == bs && oi < bi)) { bs = os; bi = oi; }
        if (h == 0) {
            sInd[row] = bi;
            ind_out[r0 + row] = (float)bi;
        }
    }
    __syncthreads();

    // ---- gather -> out, diff accumulation (R2-proven) ----
    {
        int r = tid >> 1, h = tid & 1;
        int jb = sInd[r];
        const float4* qp = reinterpret_cast<const float4*>(g_EN + jb * DIMD + h * 128);
        const float4* xp = reinterpret_cast<const float4*>(input + (r0 + r) * DIMD + h * 128);
        float4* op = reinterpret_cast<float4*>(out + (r0 + r) * DIMD + h * 128);
        float fsum = 0.f;
#pragma unroll 8
        for (int k = 0; k < 32; k++) {
            float4 q = qp[k], x = xp[k];
            op[k] = q;
            float dx = q.x - x.x, dy = q.y - x.y, dz = q.z - x.z, dw = q.w - x.w;
            fsum += dx * dx + dy * dy + dz * dz + dw * dw;
        }
        dred[tid] = (double)fsum;
    }
    __syncthreads();
    for (int o = 128; o > 0; o >>= 1) { if (tid < o) dred[tid] += dred[tid + o]; __syncthreads(); }
    if (tid == 0) g_partials[blockIdx.x] = dred[0];
}

// ---------------- final: loss = diff - entropy/E^2 ----------------
__global__ void k_final(float* __restrict__ loss_out, int nblocks, long n) {
    __shared__ double red[256];
    int t = threadIdx.x;
    double s = 0.0;
    for (int i = t; i < nblocks; i += 256) s += g_partials[i];
    red[t] = s; __syncthreads();
    for (int o = 128; o > 0; o >>= 1) { if (t < o) red[t] += red[t + o]; __syncthreads(); }
    if (t == 0) {
        double diff = red[0] / (double)n;
        loss_out[0] = (float)(diff - g_entropy / ((double)NEMB * (double)NEMB));
    }
}

extern "C" void kernel_launch(void* const* d_in, const int* in_sizes, int n_in,
                              void* d_out, int out_size) {
    const float* input = (const float*)d_in[0];
    const float* emb   = (const float*)d_in[1];
    long n     = (long)in_sizes[0];        // 33554432
    int  nrows = (int)(n / DIMD);          // 131072
    int  nblk  = nrows / TM;               // 1024
    float* out    = (float*)d_out;
    float* loss_p = out + n;               // layout: [out | loss | embed_ind]
    float* ind_p  = out + n + 1;

    cudaFuncSetAttribute(k_main, cudaFuncAttributeMaxDynamicSharedMemorySize, SMEM_REQ);
    k_norm   <<<NEMB, 64>>>(emb);
    k_entropy<<<1, 256>>>();
    k_prepB  <<<512, 256>>>();
    k_main   <<<nblk, 256, SMEM_REQ>>>(input, out, ind_p);
    k_final  <<<1, 256>>>(loss_p, nblk, n);
}